// round 9
// baseline (speedup 1.0000x reference)
#include <cuda_runtime.h>
#include <cuda_bf16.h>

// out[i] = exp(-||x_i-y_i||^2) * net(x_i) * net(y_i)
// net: 9x { z = tanh(z@W^T + b)*s + t } (2->2) folded to z = tanh(Az+c), head 2->1.
//
// R8: MUFU-bound baseline (37 MUFU/pair, 72us floor). Offload layer 4's tanh to an
// FMA-pipe rational poly (-4 MUFU/pair -> 2.06 cyc/pair floor ~= 64.5us), but with
// 1 pair/thread (4 chains) + rolled pair loop to keep regs <= 42 so occupancy
// stays at >= 6 CTAs/SM (48 of 64 warps). R7 failed because 8 live chains + poly
// temps hit 59 regs -> 32 warps -> latency-bound.

#define TPB 256
#define PAIRS 4

__device__ __forceinline__ float fast_tanh(float x) {
    float y;
    asm("tanh.approx.f32 %0, %1;" : "=f"(y) : "f"(x));
    return y;
}

// FMA/ALU-pipe tanh: Eigen 13/6 rational, reciprocal via bit-trick + 2 Newton.
__device__ __forceinline__ float tanh_poly(float x) {
    x = fminf(fmaxf(x, -7.90531111f), 7.90531111f);
    float x2 = x * x;
    float p = -2.76076847742355e-16f;
    p = fmaf(p, x2, 2.00018790482477e-13f);
    p = fmaf(p, x2, -8.60467152213735e-11f);
    p = fmaf(p, x2, 5.12229709037114e-08f);
    p = fmaf(p, x2, 1.48572235717979e-05f);
    p = fmaf(p, x2, 6.37261928875436e-04f);
    p = fmaf(p, x2, 4.89352455891786e-03f);
    float num = p * x;
    float q = 1.19825839466702e-06f;
    q = fmaf(q, x2, 1.18534705686654e-04f);
    q = fmaf(q, x2, 2.26843463243900e-03f);
    q = fmaf(q, x2, 4.89352518554385e-03f);
    float r = __int_as_float(0x7EF311C3 - __float_as_int(q));  // ~1/q
    r = r * fmaf(-q, r, 2.0f);
    r = r * fmaf(-q, r, 2.0f);
    return num * r;
}

__global__ __launch_bounds__(TPB, 6)
void fraud_kernel(const float2* __restrict__ x2,
                  const float2* __restrict__ y2,
                  const float* __restrict__ W0,
                  const float* __restrict__ b0,
                  const float* __restrict__ scale0,
                  const float* __restrict__ shift0,
                  const float* __restrict__ Ws,
                  const float* __restrict__ bs,
                  const float* __restrict__ scales,
                  const float* __restrict__ shifts,
                  const float* __restrict__ Wf,
                  const float* __restrict__ bf,
                  float* __restrict__ out,
                  int n)
{
    __shared__ float4 sW4[9];   // folded weights (w00,w01,w10,w11)
    __shared__ float2 sC2[9];   // folded biases  (c0,c1)
    __shared__ float4 sF4;      // folded head    (f0,f1,fb,-)

    const int tid = threadIdx.x;

    // fold scale/shift of layer l-1 into layer l's (W,b); head folds layer 8's
    if (tid < 9) {
        const float* W = (tid == 0) ? W0 : (Ws + (tid - 1) * 4);
        const float* B = (tid == 0) ? b0 : (bs + (tid - 1) * 2);
        float ps0 = 1.f, ps1 = 1.f, pt0 = 0.f, pt1 = 0.f;
        if (tid == 1) {
            ps0 = scale0[0]; ps1 = scale0[1];
            pt0 = shift0[0]; pt1 = shift0[1];
        } else if (tid >= 2) {
            ps0 = scales[(tid - 2) * 2 + 0]; ps1 = scales[(tid - 2) * 2 + 1];
            pt0 = shifts[(tid - 2) * 2 + 0]; pt1 = shifts[(tid - 2) * 2 + 1];
        }
        float4 w;
        w.x = W[0] * ps0; w.y = W[1] * ps1;
        w.z = W[2] * ps0; w.w = W[3] * ps1;
        sW4[tid] = w;
        float2 c;
        c.x = B[0] + W[0] * pt0 + W[1] * pt1;
        c.y = B[1] + W[2] * pt0 + W[3] * pt1;
        sC2[tid] = c;
    } else if (tid == 9) {
        float s0 = scales[14], s1 = scales[15];
        float t0 = shifts[14], t1 = shifts[15];
        float4 f;
        f.x = Wf[0] * s0;
        f.y = Wf[1] * s1;
        f.z = bf[0] + Wf[0] * t0 + Wf[1] * t1;
        f.w = 0.f;
        sF4 = f;
    }
    __syncthreads();

    int i = blockIdx.x * (TPB * PAIRS) + tid;

    #pragma unroll 1
    for (int p = 0; p < PAIRS; p++, i += TPB) {
        if (i < n) {
            float2 xv = x2[i];
            float2 yv = y2[i];

            float dx = xv.x - yv.x;
            float dy = xv.y - yv.y;
            float rbf = __expf(-fmaf(dx, dx, dy * dy));

            float a0 = xv.x, a1 = xv.y;   // net(x)
            float b0_ = yv.x, b1_ = yv.y; // net(y)

            // layers 0..3 on MUFU
            #pragma unroll 1
            for (int l = 0; l < 4; l++) {
                float4 W = sW4[l];
                float2 C = sC2[l];
                float u0 = fmaf(a0,  W.x, fmaf(a1,  W.y, C.x));
                float u1 = fmaf(a0,  W.z, fmaf(a1,  W.w, C.y));
                float v0 = fmaf(b0_, W.x, fmaf(b1_, W.y, C.x));
                float v1 = fmaf(b0_, W.z, fmaf(b1_, W.w, C.y));
                a0  = fast_tanh(u0); a1  = fast_tanh(u1);
                b0_ = fast_tanh(v0); b1_ = fast_tanh(v1);
            }

            // layer 4 on the FMA pipe (poly tanh, no MUFU)
            {
                float4 W = sW4[4];
                float2 C = sC2[4];
                float u0 = fmaf(a0,  W.x, fmaf(a1,  W.y, C.x));
                float u1 = fmaf(a0,  W.z, fmaf(a1,  W.w, C.y));
                float v0 = fmaf(b0_, W.x, fmaf(b1_, W.y, C.x));
                float v1 = fmaf(b0_, W.z, fmaf(b1_, W.w, C.y));
                a0  = tanh_poly(u0); a1  = tanh_poly(u1);
                b0_ = tanh_poly(v0); b1_ = tanh_poly(v1);
            }

            // layers 5..8 on MUFU
            #pragma unroll 1
            for (int l = 5; l < 9; l++) {
                float4 W = sW4[l];
                float2 C = sC2[l];
                float u0 = fmaf(a0,  W.x, fmaf(a1,  W.y, C.x));
                float u1 = fmaf(a0,  W.z, fmaf(a1,  W.w, C.y));
                float v0 = fmaf(b0_, W.x, fmaf(b1_, W.y, C.x));
                float v1 = fmaf(b0_, W.z, fmaf(b1_, W.w, C.y));
                a0  = fast_tanh(u0); a1  = fast_tanh(u1);
                b0_ = fast_tanh(v0); b1_ = fast_tanh(v1);
            }

            float4 F = sF4;
            float fx = fmaf(a0,  F.x, fmaf(a1,  F.y, F.z));
            float fy = fmaf(b0_, F.x, fmaf(b1_, F.y, F.z));

            out[i] = rbf * fx * fy;
        }
    }
}

extern "C" void kernel_launch(void* const* d_in, const int* in_sizes, int n_in,
                              void* d_out, int out_size)
{
    const float2* x2     = (const float2*)d_in[0];
    const float2* y2     = (const float2*)d_in[1];
    const float*  W0     = (const float*)d_in[2];
    const float*  b0     = (const float*)d_in[3];
    const float*  scale0 = (const float*)d_in[4];
    const float*  shift0 = (const float*)d_in[5];
    const float*  Ws     = (const float*)d_in[6];
    const float*  bs     = (const float*)d_in[7];
    const float*  scales = (const float*)d_in[8];
    const float*  shifts = (const float*)d_in[9];
    const float*  Wf     = (const float*)d_in[10];
    const float*  bf     = (const float*)d_in[11];
    float* out = (float*)d_out;

    int n = in_sizes[0] / 2;            // pairs
    int per_block = TPB * PAIRS;
    int blocks = (n + per_block - 1) / per_block;

    fraud_kernel<<<blocks, TPB>>>(x2, y2, W0, b0, scale0, shift0,
                                  Ws, bs, scales, shifts, Wf, bf, out, n);
}

// round 11
// speedup vs baseline: 1.2275x; 1.2275x over previous
#include <cuda_runtime.h>
#include <cuda_fp16.h>

// out[i] = exp(-||x_i-y_i||^2) * net(x_i) * net(y_i)
// net: 9x { z = tanh(z@W^T+b)*s+t } (2->2) folded to z = tanh(Az+c), head 2->1.
//
// R11 (= R10 + rename fix): MUFU-count reduction via tanh.approx.f16x2. The two
// nets (net(x), net(y)) ride in the two halves of __half2 state regs; layers 0..7
// are 4 HFMA2 + 2 MUFU each. Layer 8 + head + rbf stay f32.
// MUFU/pair: 37 -> 21  => floor ~41us (was 72us).

#define TPB 256
#define PAIRS 4

__device__ __forceinline__ float fast_tanh(float x) {
    float y;
    asm("tanh.approx.f32 %0, %1;" : "=f"(y) : "f"(x));
    return y;
}

__device__ __forceinline__ __half2 h2tanh_fast(__half2 v) {
    unsigned r, a = *reinterpret_cast<unsigned*>(&v);
    asm("tanh.approx.f16x2 %0, %1;" : "=r"(r) : "r"(a));
    return *reinterpret_cast<__half2*>(&r);
}

// per-f16-layer params: 4 duplicated weight h2s + 2 duplicated bias h2s (+pad), 32B
struct __align__(16) LayerH {
    __half2 w00, w01, w10, w11;   // (w,w) duplicated
    __half2 c0, c1;               // (c,c) duplicated
    __half2 pad0, pad1;
};

__global__ __launch_bounds__(TPB, 8)
void fraud_kernel(const float2* __restrict__ x2,
                  const float2* __restrict__ y2,
                  const float* __restrict__ W0,
                  const float* __restrict__ b0,
                  const float* __restrict__ scale0,
                  const float* __restrict__ shift0,
                  const float* __restrict__ Ws,
                  const float* __restrict__ bs,
                  const float* __restrict__ scales,
                  const float* __restrict__ shifts,
                  const float* __restrict__ Wf,
                  const float* __restrict__ bf,
                  float* __restrict__ out,
                  int n)
{
    __shared__ LayerH sH[8];     // f16 layers 0..7
    __shared__ float4 sW8;       // f32 layer 8 weights
    __shared__ float2 sC8;       // f32 layer 8 bias
    __shared__ float4 sF4;       // folded head (f0,f1,fb,-)

    const int tid = threadIdx.x;

    // fold scale/shift of layer l-1 into layer l's (W,b); head folds layer 8's.
    // layer indices: 0 = input layer (W0), 1..8 = hidden Ws[0..7].
    if (tid < 9) {
        const float* W = (tid == 0) ? W0 : (Ws + (tid - 1) * 4);
        const float* B = (tid == 0) ? b0 : (bs + (tid - 1) * 2);
        float ps0 = 1.f, ps1 = 1.f, pt0 = 0.f, pt1 = 0.f;
        if (tid == 1) {
            ps0 = scale0[0]; ps1 = scale0[1];
            pt0 = shift0[0]; pt1 = shift0[1];
        } else if (tid >= 2) {
            ps0 = scales[(tid - 2) * 2 + 0]; ps1 = scales[(tid - 2) * 2 + 1];
            pt0 = shifts[(tid - 2) * 2 + 0]; pt1 = shifts[(tid - 2) * 2 + 1];
        }
        float w00 = W[0] * ps0, w01 = W[1] * ps1;
        float w10 = W[2] * ps0, w11 = W[3] * ps1;
        float c0 = B[0] + W[0] * pt0 + W[1] * pt1;
        float c1 = B[1] + W[2] * pt0 + W[3] * pt1;

        if (tid < 8) {
            LayerH L;
            L.w00 = __float2half2_rn(w00);
            L.w01 = __float2half2_rn(w01);
            L.w10 = __float2half2_rn(w10);
            L.w11 = __float2half2_rn(w11);
            L.c0  = __float2half2_rn(c0);
            L.c1  = __float2half2_rn(c1);
            L.pad0 = __float2half2_rn(0.f);
            L.pad1 = __float2half2_rn(0.f);
            sH[tid] = L;
        } else {
            float4 wf; wf.x = w00; wf.y = w01; wf.z = w10; wf.w = w11;
            sW8 = wf;
            float2 cf; cf.x = c0; cf.y = c1;
            sC8 = cf;
        }
    } else if (tid == 9) {
        float s0 = scales[14], s1 = scales[15];
        float t0 = shifts[14], t1 = shifts[15];
        float4 f;
        f.x = Wf[0] * s0;
        f.y = Wf[1] * s1;
        f.z = bf[0] + Wf[0] * t0 + Wf[1] * t1;
        f.w = 0.f;
        sF4 = f;
    }
    __syncthreads();

    int i = blockIdx.x * (TPB * PAIRS) + tid;

    #pragma unroll 1
    for (int p = 0; p < PAIRS; p++, i += TPB) {
        if (i < n) {
            float2 xv = x2[i];
            float2 yv = y2[i];

            float dx = xv.x - yv.x;
            float dy = xv.y - yv.y;
            float rbf = __expf(-fmaf(dx, dx, dy * dy));

            // halves = (net(x), net(y)); z0 = unit0, z1 = unit1
            __half2 z0 = __floats2half2_rn(xv.x, yv.x);
            __half2 z1 = __floats2half2_rn(xv.y, yv.y);

            // layers 0..7 in f16x2: 4 HFMA2 + 2 MUFU each
            #pragma unroll 1
            for (int l = 0; l < 8; l++) {
                const LayerH L = sH[l];
                __half2 u0 = __hfma2(z0, L.w00, __hfma2(z1, L.w01, L.c0));
                __half2 u1 = __hfma2(z0, L.w10, __hfma2(z1, L.w11, L.c1));
                z0 = h2tanh_fast(u0);
                z1 = h2tanh_fast(u1);
            }

            // unpack; layer 8 + head in f32
            float ax0 = __low2float(z0),  ay0 = __high2float(z0);
            float ax1 = __low2float(z1),  ay1 = __high2float(z1);

            float4 W = sW8;
            float2 C = sC8;
            float ux0 = fmaf(ax0, W.x, fmaf(ax1, W.y, C.x));
            float ux1 = fmaf(ax0, W.z, fmaf(ax1, W.w, C.y));
            float uy0 = fmaf(ay0, W.x, fmaf(ay1, W.y, C.x));
            float uy1 = fmaf(ay0, W.z, fmaf(ay1, W.w, C.y));
            ax0 = fast_tanh(ux0); ax1 = fast_tanh(ux1);
            ay0 = fast_tanh(uy0); ay1 = fast_tanh(uy1);

            float4 F = sF4;
            float fx = fmaf(ax0, F.x, fmaf(ax1, F.y, F.z));
            float fy = fmaf(ay0, F.x, fmaf(ay1, F.y, F.z));

            out[i] = rbf * fx * fy;
        }
    }
}

extern "C" void kernel_launch(void* const* d_in, const int* in_sizes, int n_in,
                              void* d_out, int out_size)
{
    const float2* x2     = (const float2*)d_in[0];
    const float2* y2     = (const float2*)d_in[1];
    const float*  W0     = (const float*)d_in[2];
    const float*  b0     = (const float*)d_in[3];
    const float*  scale0 = (const float*)d_in[4];
    const float*  shift0 = (const float*)d_in[5];
    const float*  Ws     = (const float*)d_in[6];
    const float*  bs     = (const float*)d_in[7];
    const float*  scales = (const float*)d_in[8];
    const float*  shifts = (const float*)d_in[9];
    const float*  Wf     = (const float*)d_in[10];
    const float*  bf     = (const float*)d_in[11];
    float* out = (float*)d_out;

    int n = in_sizes[0] / 2;            // pairs
    int per_block = TPB * PAIRS;
    int blocks = (n + per_block - 1) / per_block;

    fraud_kernel<<<blocks, TPB>>>(x2, y2, W0, b0, scale0, shift0,
                                  Ws, bs, scales, shifts, Wf, bf, out, n);
}